// round 16
// baseline (speedup 1.0000x reference)
#include <cuda_runtime.h>
#include <cuda_bf16.h>

// Problem constants
#define BB 256
#define TT 512
#define FF 128
#define HH 256
#define NQ 4

#define L2E 1.4426950408889634f

__device__ __forceinline__ float fast_rcp(float x) {
    float r;
    asm("rcp.approx.ftz.f32 %0, %1;" : "=f"(r) : "f"(x));
    return r;
}
__device__ __forceinline__ float ex2f(float x) {
    float r;
    asm("ex2.approx.ftz.f32 %0, %1;" : "=f"(r) : "f"(x));
    return r;
}
// ---- packed f32x2 helpers (sm_100+/sm_103a) ----
__device__ __forceinline__ unsigned long long pk2(float lo, float hi) {
    unsigned long long r;
    asm("mov.b64 %0, {%1, %2};" : "=l"(r) : "f"(lo), "f"(hi));
    return r;
}
__device__ __forceinline__ void upk2(unsigned long long v, float& lo, float& hi) {
    asm("mov.b64 {%0, %1}, %2;" : "=f"(lo), "=f"(hi) : "l"(v));
}
__device__ __forceinline__ unsigned long long fma2(unsigned long long a, unsigned long long b, unsigned long long c) {
    unsigned long long d;
    asm("fma.rn.f32x2 %0, %1, %2, %3;" : "=l"(d) : "l"(a), "l"(b), "l"(c));
    return d;
}
__device__ __forceinline__ unsigned long long mul2(unsigned long long a, unsigned long long b) {
    unsigned long long d;
    asm("mul.rn.f32x2 %0, %1, %2;" : "=l"(d) : "l"(a), "l"(b));
    return d;
}
__device__ __forceinline__ unsigned long long add2(unsigned long long a, unsigned long long b) {
    unsigned long long d;
    asm("add.rn.f32x2 %0, %1, %2;" : "=l"(d) : "l"(a), "l"(b));
    return d;
}

// Named barrier over a 128-thread engine
__device__ __forceinline__ void bar_sync(int id) { asm volatile("bar.sync %0, 128;" :: "r"(id) : "memory"); }

__global__ __launch_bounds__(256, 2)
void qlstm_kernel(const float* __restrict__ x,      // [B, T, F]
                  const float* __restrict__ W_in,   // [H+F, NQ]
                  const float* __restrict__ b_in,   // [NQ]
                  const float* __restrict__ Wq,     // [4, NQ, NQ]
                  const float* __restrict__ bq,     // [4, NQ]
                  const float* __restrict__ W_out,  // [NQ, H]
                  const float* __restrict__ b_out,  // [H]
                  float* __restrict__ out)          // [B*T*H] + [B*H] + [B*H]
{
    // two independent engines (g=0,1), one batch each, 4 warps / 128 threads each
    __shared__ float4 sxp[2][TT + 1];                // x-projection + b_in per engine (+pad)
    __shared__ float4 sWx[FF];                       // W_in rows H..H+F-1
    __shared__ __align__(16) float spartf[2][2][4][8]; // [parity][g][comp][8 partials]
    __shared__ __align__(16) float sqw[2][4][16];    // [g][warp][r*4+k] q exchange (r-major)
    __shared__ float  sWq[64];
    __shared__ float  sbq[16];

    const int tid  = threadIdx.x;
    const int lane = tid & 31;
    const int g    = tid >> 7;          // engine / batch-within-CTA
    const int j    = tid & 127;         // thread within engine
    const int wg   = (tid >> 5) & 3;    // warp within engine
    const int b    = blockIdx.x * 2 + g;
    const int xwg  = g ? 3 : 0;         // designated xv-folding warp (SMSP balance)

    // ---- stage small weights into SMEM ----
    if (tid < FF) sWx[tid] = *reinterpret_cast<const float4*>(W_in + (size_t)(HH + tid) * NQ);
    if (tid < 64) sWq[tid] = Wq[tid];
    if (tid < 16) sbq[tid] = bq[tid];
    const float4 b4 = *reinterpret_cast<const float4*>(b_in);
    __syncthreads();

    // ---- prologue: each engine fills its x-projection (recurrence-free) ----
    for (int t = j; t < TT; t += 128) {
        const float4* xr = reinterpret_cast<const float4*>(x + ((size_t)b * TT + t) * FF);
        float4 acc = b4;
        #pragma unroll 8
        for (int f4 = 0; f4 < FF / 4; f4++) {
            float4 xv = xr[f4];
            float4 w0 = sWx[4 * f4 + 0];
            float4 w1 = sWx[4 * f4 + 1];
            float4 w2 = sWx[4 * f4 + 2];
            float4 w3 = sWx[4 * f4 + 3];
            acc.x = fmaf(xv.x, w0.x, fmaf(xv.y, w1.x, fmaf(xv.z, w2.x, fmaf(xv.w, w3.x, acc.x))));
            acc.y = fmaf(xv.x, w0.y, fmaf(xv.y, w1.y, fmaf(xv.z, w2.y, fmaf(xv.w, w3.y, acc.y))));
            acc.z = fmaf(xv.x, w0.z, fmaf(xv.y, w1.z, fmaf(xv.z, w2.z, fmaf(xv.w, w3.z, acc.z))));
            acc.w = fmaf(xv.x, w0.w, fmaf(xv.y, w1.w, fmaf(xv.z, w2.w, fmaf(xv.w, w3.w, acc.w))));
        }
        sxp[g][t] = acc;
    }
    if (j == 0) sxp[g][TT] = b4;   // pad entry for the t+1 prefetch at t=TT-1

    // ---- per-thread persistent state & weights: units u0=2j, u1=2j+1 ----
    const int u0 = 2 * j;
    const int u1 = u0 + 1;
    const float4 wha = *reinterpret_cast<const float4*>(W_in + (size_t)u0 * NQ);
    const float4 whb = *reinterpret_cast<const float4*>(W_in + (size_t)u1 * NQ);

    // packed (w,w) output weights & biases per unit (loop-invariant)
    const unsigned long long woa0 = pk2(W_out[0 * HH + u0], W_out[0 * HH + u0]);
    const unsigned long long woa1 = pk2(W_out[1 * HH + u0], W_out[1 * HH + u0]);
    const unsigned long long woa2 = pk2(W_out[2 * HH + u0], W_out[2 * HH + u0]);
    const unsigned long long woa3 = pk2(W_out[3 * HH + u0], W_out[3 * HH + u0]);
    const unsigned long long wob0 = pk2(W_out[0 * HH + u1], W_out[0 * HH + u1]);
    const unsigned long long wob1 = pk2(W_out[1 * HH + u1], W_out[1 * HH + u1]);
    const unsigned long long wob2 = pk2(W_out[2 * HH + u1], W_out[2 * HH + u1]);
    const unsigned long long wob3 = pk2(W_out[3 * HH + u1], W_out[3 * HH + u1]);
    const unsigned long long boa2 = pk2(b_out[u0], b_out[u0]);
    const unsigned long long bob2 = pk2(b_out[u1], b_out[u1]);
    const unsigned long long cIF  = pk2(-L2E, -L2E);          // (i,f): exp(-z)
    const unsigned long long cGO  = pk2(2.0f * L2E, -L2E);    // (g,o): exp(2z), exp(-z)

    // phase-B per-lane constants (lanes replicate mod 16); store r-major
    const int ql = lane & 15;
    const int qk = ql >> 2;                       // gate k
    const int qr = ql & 3;                        // multiplier index r
    const int qbase = (qk << 4) + qr;             // k*16 + r  (Wq layout)
    const float qw0 = sWq[qbase +  0];
    const float qw1 = sWq[qbase +  4];
    const float qw2 = sWq[qbase +  8];
    const float qw3 = sWq[qbase + 12];
    const float qb  = sbq[ql];
    const int qstore = (qr << 2) | qk;            // r*4 + k  (r-major exchange layout)

    float ha = 0.0f, ca = 0.0f;   // unit u0
    float hb = 0.0f, cb = 0.0f;   // unit u1
    float* hs = out + ((size_t)b * TT) * HH + u0;

    const int bid = 1 + g;

    __syncthreads();  // sxp ready (block-wide, once)

    // software-pipelined x-projection for the designated warp
    float4 xv = make_float4(0.f, 0.f, 0.f, 0.f);
    if (wg == xwg) xv = sxp[g][0];

    #pragma unroll 2
    for (int t = 0; t < TT; t++) {
        const int pr = t & 1;

        // ---- phase A: 4-component butterfly, 8 SHFL (stop at off=2) ----
        {
            float p0 = fmaf(hb, whb.x, ha * wha.x);
            float p1 = fmaf(hb, whb.y, ha * wha.y);
            float p2 = fmaf(hb, whb.z, ha * wha.z);
            float p3 = fmaf(hb, whb.w, ha * wha.w);
            if (wg == xwg) {
                p0 = fmaf(xv.x, 0.03125f, p0);   // exact 2^-5 scale
                p1 = fmaf(xv.y, 0.03125f, p1);
                p2 = fmaf(xv.z, 0.03125f, p2);
                p3 = fmaf(xv.w, 0.03125f, p3);
            }
            float a0 = p0 + __shfl_xor_sync(0xffffffffu, p0, 16);
            float a1 = p1 + __shfl_xor_sync(0xffffffffu, p1, 16);
            float a2 = p2 + __shfl_xor_sync(0xffffffffu, p2, 16);
            float a3 = p3 + __shfl_xor_sync(0xffffffffu, p3, 16);
            float v0 = (lane & 16) ? a2 : a0;
            float v1 = (lane & 16) ? a3 : a1;
            v0 += __shfl_xor_sync(0xffffffffu, v0, 8);
            v1 += __shfl_xor_sync(0xffffffffu, v1, 8);
            float v = (lane & 8) ? v1 : v0;
            v += __shfl_xor_sync(0xffffffffu, v, 4);
            v += __shfl_xor_sync(0xffffffffu, v, 2);
            // lanes l and l^1 now hold complementary 16-lane partials of comp (lane>>3)
            if ((lane & 6) == 0)
                spartf[pr][g][lane >> 3][wg * 2 + (lane & 1)] = v;
        }

        // ---- single engine-wide barrier per step ----
        bar_sync(bid);

        // ---- phase B (redundant on all 4 warps): 16 q values, packed 8-wide gather ----
        {
            const ulonglong2* sp2 = reinterpret_cast<const ulonglong2*>(&spartf[pr][g][0][0]);
            ulonglong2 d0 = sp2[0], d1 = sp2[1];   // comp 0
            ulonglong2 d2 = sp2[2], d3 = sp2[3];   // comp 1
            ulonglong2 d4 = sp2[4], d5 = sp2[5];   // comp 2
            ulonglong2 d6 = sp2[6], d7 = sp2[7];   // comp 3
            unsigned long long s0 = add2(add2(d0.x, d0.y), add2(d1.x, d1.y));
            unsigned long long s1 = add2(add2(d2.x, d2.y), add2(d3.x, d3.y));
            unsigned long long s2 = add2(add2(d4.x, d4.y), add2(d5.x, d5.y));
            unsigned long long s3 = add2(add2(d6.x, d6.y), add2(d7.x, d7.y));
            float l0, h0, l1, h1, l2, h2, l3, h3;
            upk2(s0, l0, h0); upk2(s1, l1, h1); upk2(s2, l2, h2); upk2(s3, l3, h3);
            float y0 = l0 + h0;
            float y1 = l1 + h1;
            float y2 = l2 + h2;
            float y3 = l3 + h3;
            float acc = (fmaf(y0, qw0, qb) + y1 * qw1) + (y2 * qw2 + y3 * qw3);
            float e = ex2f(acc * (2.0f * L2E));              // tanh via exp2
            sqw[g][wg][qstore] = (e - 1.0f) * fast_rcp(e + 1.0f);
        }
        __syncwarp();

        // ---- phase C: packed z-projection (split chains) + unmerged-rcp gates ----
        const ulonglong2* qq = reinterpret_cast<const ulonglong2*>(sqw[g][wg]);
        ulonglong2 q0p = qq[0], q1p = qq[1], q2p = qq[2], q3p = qq[3];

        unsigned long long zifa = add2(fma2(q1p.x, woa1, fma2(q0p.x, woa0, boa2)),
                                       fma2(q3p.x, woa3, mul2(q2p.x, woa2)));
        unsigned long long zgoa = add2(fma2(q1p.y, woa1, fma2(q0p.y, woa0, boa2)),
                                       fma2(q3p.y, woa3, mul2(q2p.y, woa2)));
        unsigned long long zifb = add2(fma2(q1p.x, wob1, fma2(q0p.x, wob0, bob2)),
                                       fma2(q3p.x, wob3, mul2(q2p.x, wob2)));
        unsigned long long zgob = add2(fma2(q1p.y, wob1, fma2(q0p.y, wob0, bob2)),
                                       fma2(q3p.y, wob3, mul2(q2p.y, wob2)));

        // packed exp-argument scaling, then scalar EX2
        unsigned long long aifa = mul2(zifa, cIF);
        unsigned long long agoa = mul2(zgoa, cGO);
        unsigned long long aifb = mul2(zifb, cIF);
        unsigned long long agob = mul2(zgob, cGO);
        float t00, t01, t02, t03, t10, t11, t12, t13;
        upk2(aifa, t00, t01); upk2(agoa, t02, t03);
        upk2(aifb, t10, t11); upk2(agob, t12, t13);
        float e00 = ex2f(t00);   // exp(-zi_a)
        float e01 = ex2f(t01);   // exp(-zf_a)
        float e02 = ex2f(t02);   // exp(2zg_a)
        float e03 = ex2f(t03);   // exp(-zo_a)
        float e10 = ex2f(t10);
        float e11 = ex2f(t11);
        float e12 = ex2f(t12);
        float e13 = ex2f(t13);

        // c-updates, one rcp per unit (shorter chain than merged; MUFU slack available)
        float D1a = 1.0f + e01;
        float D2a = (1.0f + e00) * (e02 + 1.0f);
        float numa = fmaf(ca, D2a, (e02 - 1.0f) * D1a);
        ca = numa * fast_rcp(D1a * D2a);
        float D1b = 1.0f + e11;
        float D2b = (1.0f + e10) * (e12 + 1.0f);
        float numb = fmaf(cb, D2b, (e12 - 1.0f) * D1b);
        cb = numb * fast_rcp(D1b * D2b);

        // h-updates, one rcp per unit
        float eca = ex2f(ca * (2.0f * L2E));
        float ecb = ex2f(cb * (2.0f * L2E));
        ha = (eca - 1.0f) * fast_rcp((1.0f + e03) * (eca + 1.0f));
        hb = (ecb - 1.0f) * fast_rcp((1.0f + e13) * (ecb + 1.0f));

        // prefetch next x-projection during the C tail (address is recurrence-free)
        if (wg == xwg) xv = sxp[g][t + 1];

        __stcs(reinterpret_cast<float2*>(hs + (size_t)t * HH), make_float2(ha, hb));
    }

    // ---- final states ----
    const size_t seq_elems = (size_t)BB * TT * HH;
    *reinterpret_cast<float2*>(out + seq_elems + (size_t)b * HH + u0) = make_float2(ha, hb);
    *reinterpret_cast<float2*>(out + seq_elems + (size_t)BB * HH + (size_t)b * HH + u0) = make_float2(ca, cb);
}

extern "C" void kernel_launch(void* const* d_in, const int* in_sizes, int n_in,
                              void* d_out, int out_size) {
    const float* x     = (const float*)d_in[0];
    const float* W_in  = (const float*)d_in[1];
    const float* b_in  = (const float*)d_in[2];
    const float* Wq    = (const float*)d_in[3];
    const float* bq    = (const float*)d_in[4];
    const float* W_out = (const float*)d_in[5];
    const float* b_out = (const float*)d_in[6];
    float* out = (float*)d_out;
    qlstm_kernel<<<BB / 2, 256>>>(x, W_in, b_in, Wq, bq, W_out, b_out, out);
}

// round 17
// speedup vs baseline: 1.6719x; 1.6719x over previous
#include <cuda_runtime.h>
#include <cuda_bf16.h>

// Problem constants
#define BB 256
#define TT 512
#define FF 128
#define HH 256
#define NQ 4

#define L2E 1.4426950408889634f

__device__ __forceinline__ float fast_rcp(float x) {
    float r;
    asm("rcp.approx.ftz.f32 %0, %1;" : "=f"(r) : "f"(x));
    return r;
}
__device__ __forceinline__ float ex2f(float x) {
    float r;
    asm("ex2.approx.ftz.f32 %0, %1;" : "=f"(r) : "f"(x));
    return r;
}
// ---- packed f32x2 helpers (sm_100+/sm_103a) ----
__device__ __forceinline__ unsigned long long pk2(float lo, float hi) {
    unsigned long long r;
    asm("mov.b64 %0, {%1, %2};" : "=l"(r) : "f"(lo), "f"(hi));
    return r;
}
__device__ __forceinline__ void upk2(unsigned long long v, float& lo, float& hi) {
    asm("mov.b64 {%0, %1}, %2;" : "=f"(lo), "=f"(hi) : "l"(v));
}
__device__ __forceinline__ unsigned long long fma2(unsigned long long a, unsigned long long b, unsigned long long c) {
    unsigned long long d;
    asm("fma.rn.f32x2 %0, %1, %2, %3;" : "=l"(d) : "l"(a), "l"(b), "l"(c));
    return d;
}
__device__ __forceinline__ unsigned long long mul2(unsigned long long a, unsigned long long b) {
    unsigned long long d;
    asm("mul.rn.f32x2 %0, %1, %2;" : "=l"(d) : "l"(a), "l"(b));
    return d;
}
__device__ __forceinline__ unsigned long long add2(unsigned long long a, unsigned long long b) {
    unsigned long long d;
    asm("add.rn.f32x2 %0, %1, %2;" : "=l"(d) : "l"(a), "l"(b));
    return d;
}

// Named barrier over a 128-thread engine
__device__ __forceinline__ void bar_sync(int id) { asm volatile("bar.sync %0, 128;" :: "r"(id) : "memory"); }

__global__ __launch_bounds__(256, 2)
void qlstm_kernel(const float* __restrict__ x,      // [B, T, F]
                  const float* __restrict__ W_in,   // [H+F, NQ]
                  const float* __restrict__ b_in,   // [NQ]
                  const float* __restrict__ Wq,     // [4, NQ, NQ]
                  const float* __restrict__ bq,     // [4, NQ]
                  const float* __restrict__ W_out,  // [NQ, H]
                  const float* __restrict__ b_out,  // [H]
                  float* __restrict__ out)          // [B*T*H] + [B*H] + [B*H]
{
    // two independent engines (g=0,1), one batch each, 4 warps / 128 threads each
    __shared__ float4 sxp[2][TT + 1];                // x-projection + b_in per engine (+pad)
    __shared__ float4 sWx[FF];                       // W_in rows H..H+F-1
    __shared__ __align__(16) float spartf[2][2][4][8]; // [parity][g][comp][8 partials]
    __shared__ __align__(16) float sqw[2][4][16];    // [g][warp][r*4+k] q exchange (r-major)
    __shared__ float  sWq[64];
    __shared__ float  sbq[16];

    const int tid  = threadIdx.x;
    const int lane = tid & 31;
    const int g    = tid >> 7;          // engine / batch-within-CTA
    const int j    = tid & 127;         // thread within engine
    const int wg   = (tid >> 5) & 3;    // warp within engine
    const int b    = blockIdx.x * 2 + g;
    const int xwg  = g ? 3 : 0;         // designated xv-folding warp (SMSP balance)

    // ---- stage small weights into SMEM ----
    if (tid < FF) sWx[tid] = *reinterpret_cast<const float4*>(W_in + (size_t)(HH + tid) * NQ);
    if (tid < 64) sWq[tid] = Wq[tid];
    if (tid < 16) sbq[tid] = bq[tid];
    const float4 b4 = *reinterpret_cast<const float4*>(b_in);
    __syncthreads();

    // ---- prologue: each engine fills its x-projection (recurrence-free) ----
    for (int t = j; t < TT; t += 128) {
        const float4* xr = reinterpret_cast<const float4*>(x + ((size_t)b * TT + t) * FF);
        float4 acc = b4;
        #pragma unroll 8
        for (int f4 = 0; f4 < FF / 4; f4++) {
            float4 xv = xr[f4];
            float4 w0 = sWx[4 * f4 + 0];
            float4 w1 = sWx[4 * f4 + 1];
            float4 w2 = sWx[4 * f4 + 2];
            float4 w3 = sWx[4 * f4 + 3];
            acc.x = fmaf(xv.x, w0.x, fmaf(xv.y, w1.x, fmaf(xv.z, w2.x, fmaf(xv.w, w3.x, acc.x))));
            acc.y = fmaf(xv.x, w0.y, fmaf(xv.y, w1.y, fmaf(xv.z, w2.y, fmaf(xv.w, w3.y, acc.y))));
            acc.z = fmaf(xv.x, w0.z, fmaf(xv.y, w1.z, fmaf(xv.z, w2.z, fmaf(xv.w, w3.z, acc.z))));
            acc.w = fmaf(xv.x, w0.w, fmaf(xv.y, w1.w, fmaf(xv.z, w2.w, fmaf(xv.w, w3.w, acc.w))));
        }
        sxp[g][t] = acc;
    }
    if (j == 0) sxp[g][TT] = b4;   // pad entry for the t+1 prefetch at t=TT-1

    // ---- per-thread persistent state & weights: units u0=2j, u1=2j+1 ----
    const int u0 = 2 * j;
    const int u1 = u0 + 1;
    const float4 wha = *reinterpret_cast<const float4*>(W_in + (size_t)u0 * NQ);
    const float4 whb = *reinterpret_cast<const float4*>(W_in + (size_t)u1 * NQ);

    // packed (w,w) output weights & biases per unit (loop-invariant)
    const unsigned long long woa0 = pk2(W_out[0 * HH + u0], W_out[0 * HH + u0]);
    const unsigned long long woa1 = pk2(W_out[1 * HH + u0], W_out[1 * HH + u0]);
    const unsigned long long woa2 = pk2(W_out[2 * HH + u0], W_out[2 * HH + u0]);
    const unsigned long long woa3 = pk2(W_out[3 * HH + u0], W_out[3 * HH + u0]);
    const unsigned long long wob0 = pk2(W_out[0 * HH + u1], W_out[0 * HH + u1]);
    const unsigned long long wob1 = pk2(W_out[1 * HH + u1], W_out[1 * HH + u1]);
    const unsigned long long wob2 = pk2(W_out[2 * HH + u1], W_out[2 * HH + u1]);
    const unsigned long long wob3 = pk2(W_out[3 * HH + u1], W_out[3 * HH + u1]);
    const unsigned long long boa2 = pk2(b_out[u0], b_out[u0]);
    const unsigned long long bob2 = pk2(b_out[u1], b_out[u1]);
    const unsigned long long cIF  = pk2(-L2E, -L2E);          // (i,f): exp(-z)
    const unsigned long long cGO  = pk2(2.0f * L2E, -L2E);    // (g,o): exp(2z), exp(-z)

    // phase-B per-lane constants (lanes replicate mod 16); store r-major.
    // Pre-scaled by 2*log2(e) so acc feeds ex2 directly (one less dependent FMUL).
    const int ql = lane & 15;
    const int qk = ql >> 2;                       // gate k
    const int qr = ql & 3;                        // multiplier index r
    const int qbase = (qk << 4) + qr;             // k*16 + r  (Wq layout)
    const float qw0 = sWq[qbase +  0] * (2.0f * L2E);
    const float qw1 = sWq[qbase +  4] * (2.0f * L2E);
    const float qw2 = sWq[qbase +  8] * (2.0f * L2E);
    const float qw3 = sWq[qbase + 12] * (2.0f * L2E);
    const float qb  = sbq[ql] * (2.0f * L2E);
    const int qstore = (qr << 2) | qk;            // r*4 + k  (r-major exchange layout)

    float ha = 0.0f, ca = 0.0f;   // unit u0
    float hb = 0.0f, cb = 0.0f;   // unit u1
    float* hs = out + ((size_t)b * TT) * HH + u0;

    const int bid = 1 + g;

    __syncthreads();  // sxp ready (block-wide, once)

    // software-pipelined x-projection for the designated warp
    float4 xv = make_float4(0.f, 0.f, 0.f, 0.f);
    if (wg == xwg) xv = sxp[g][0];

    #pragma unroll 2
    for (int t = 0; t < TT; t++) {
        const int pr = t & 1;

        // ---- phase A: 4-component butterfly, 8 SHFL (stop at off=2) ----
        {
            float p0 = fmaf(hb, whb.x, ha * wha.x);
            float p1 = fmaf(hb, whb.y, ha * wha.y);
            float p2 = fmaf(hb, whb.z, ha * wha.z);
            float p3 = fmaf(hb, whb.w, ha * wha.w);
            if (wg == xwg) {
                p0 = fmaf(xv.x, 0.03125f, p0);   // exact 2^-5 scale
                p1 = fmaf(xv.y, 0.03125f, p1);
                p2 = fmaf(xv.z, 0.03125f, p2);
                p3 = fmaf(xv.w, 0.03125f, p3);
            }
            float a0 = p0 + __shfl_xor_sync(0xffffffffu, p0, 16);
            float a1 = p1 + __shfl_xor_sync(0xffffffffu, p1, 16);
            float a2 = p2 + __shfl_xor_sync(0xffffffffu, p2, 16);
            float a3 = p3 + __shfl_xor_sync(0xffffffffu, p3, 16);
            float v0 = (lane & 16) ? a2 : a0;
            float v1 = (lane & 16) ? a3 : a1;
            v0 += __shfl_xor_sync(0xffffffffu, v0, 8);
            v1 += __shfl_xor_sync(0xffffffffu, v1, 8);
            float v = (lane & 8) ? v1 : v0;
            v += __shfl_xor_sync(0xffffffffu, v, 4);
            v += __shfl_xor_sync(0xffffffffu, v, 2);
            // lanes l and l^1 now hold complementary 16-lane partials of comp (lane>>3)
            if ((lane & 6) == 0)
                spartf[pr][g][lane >> 3][wg * 2 + (lane & 1)] = v;
        }

        // ---- single engine-wide barrier per step ----
        bar_sync(bid);

        // ---- phase B (redundant on all 4 warps): 16 q values, packed 8-wide gather ----
        {
            const ulonglong2* sp2 = reinterpret_cast<const ulonglong2*>(&spartf[pr][g][0][0]);
            ulonglong2 d0 = sp2[0], d1 = sp2[1];   // comp 0
            ulonglong2 d2 = sp2[2], d3 = sp2[3];   // comp 1
            ulonglong2 d4 = sp2[4], d5 = sp2[5];   // comp 2
            ulonglong2 d6 = sp2[6], d7 = sp2[7];   // comp 3
            unsigned long long s0 = add2(add2(d0.x, d0.y), add2(d1.x, d1.y));
            unsigned long long s1 = add2(add2(d2.x, d2.y), add2(d3.x, d3.y));
            unsigned long long s2 = add2(add2(d4.x, d4.y), add2(d5.x, d5.y));
            unsigned long long s3 = add2(add2(d6.x, d6.y), add2(d7.x, d7.y));
            float l0, h0, l1, h1, l2, h2, l3, h3;
            upk2(s0, l0, h0); upk2(s1, l1, h1); upk2(s2, l2, h2); upk2(s3, l3, h3);
            float y0 = l0 + h0;
            float y1 = l1 + h1;
            float y2 = l2 + h2;
            float y3 = l3 + h3;
            // weights pre-scaled by 2*log2(e): acc feeds ex2 directly
            float acc = (fmaf(y0, qw0, qb) + y1 * qw1) + (y2 * qw2 + y3 * qw3);
            float e = ex2f(acc);                             // tanh via exp2
            sqw[g][wg][qstore] = (e - 1.0f) * fast_rcp(e + 1.0f);
        }
        __syncwarp();

        // ---- phase C: packed z-projection (16 FFMA2) + merged-rcp gates (R14 layout) ----
        const ulonglong2* qq = reinterpret_cast<const ulonglong2*>(sqw[g][wg]);
        ulonglong2 q0p = qq[0], q1p = qq[1], q2p = qq[2], q3p = qq[3];

        unsigned long long zifa = boa2, zgoa = boa2, zifb = bob2, zgob = bob2;
        zifa = fma2(q0p.x, woa0, zifa);
        zifa = fma2(q1p.x, woa1, zifa);
        zifa = fma2(q2p.x, woa2, zifa);
        zifa = fma2(q3p.x, woa3, zifa);
        zgoa = fma2(q0p.y, woa0, zgoa);
        zgoa = fma2(q1p.y, woa1, zgoa);
        zgoa = fma2(q2p.y, woa2, zgoa);
        zgoa = fma2(q3p.y, woa3, zgoa);
        zifb = fma2(q0p.x, wob0, zifb);
        zifb = fma2(q1p.x, wob1, zifb);
        zifb = fma2(q2p.x, wob2, zifb);
        zifb = fma2(q3p.x, wob3, zifb);
        zgob = fma2(q0p.y, wob0, zgob);
        zgob = fma2(q1p.y, wob1, zgob);
        zgob = fma2(q2p.y, wob2, zgob);
        zgob = fma2(q3p.y, wob3, zgob);

        // packed exp-argument scaling, then scalar EX2
        unsigned long long aifa = mul2(zifa, cIF);
        unsigned long long agoa = mul2(zgoa, cGO);
        unsigned long long aifb = mul2(zifb, cIF);
        unsigned long long agob = mul2(zgob, cGO);
        float t00, t01, t02, t03, t10, t11, t12, t13;
        upk2(aifa, t00, t01); upk2(agoa, t02, t03);
        upk2(aifb, t10, t11); upk2(agob, t12, t13);
        float e00 = ex2f(t00);   // exp(-zi_a)
        float e01 = ex2f(t01);   // exp(-zf_a)
        float e02 = ex2f(t02);   // exp(2zg_a)
        float e03 = ex2f(t03);   // exp(-zo_a)
        float e10 = ex2f(t10);
        float e11 = ex2f(t11);
        float e12 = ex2f(t12);
        float e13 = ex2f(t13);

        // c-updates with ONE merged reciprocal
        float D1a = 1.0f + e01;
        float D2a = (1.0f + e00) * (e02 + 1.0f);
        float Da  = D1a * D2a;
        float numa = ca * D2a + (e02 - 1.0f) * D1a;
        float D1b = 1.0f + e11;
        float D2b = (1.0f + e10) * (e12 + 1.0f);
        float Db  = D1b * D2b;
        float numb = cb * D2b + (e12 - 1.0f) * D1b;
        float rc = fast_rcp(Da * Db);
        ca = numa * Db * rc;
        cb = numb * Da * rc;

        // h-updates with ONE merged reciprocal
        float eca = ex2f(ca * (2.0f * L2E));
        float ecb = ex2f(cb * (2.0f * L2E));
        float dha = (1.0f + e03) * (eca + 1.0f);
        float dhb = (1.0f + e13) * (ecb + 1.0f);
        float rh = fast_rcp(dha * dhb);
        ha = (eca - 1.0f) * dhb * rh;
        hb = (ecb - 1.0f) * dha * rh;

        // prefetch next x-projection during the C tail (address is recurrence-free)
        if (wg == xwg) xv = sxp[g][t + 1];

        __stcs(reinterpret_cast<float2*>(hs + (size_t)t * HH), make_float2(ha, hb));
    }

    // ---- final states ----
    const size_t seq_elems = (size_t)BB * TT * HH;
    *reinterpret_cast<float2*>(out + seq_elems + (size_t)b * HH + u0) = make_float2(ha, hb);
    *reinterpret_cast<float2*>(out + seq_elems + (size_t)BB * HH + (size_t)b * HH + u0) = make_float2(ca, cb);
}

extern "C" void kernel_launch(void* const* d_in, const int* in_sizes, int n_in,
                              void* d_out, int out_size) {
    const float* x     = (const float*)d_in[0];
    const float* W_in  = (const float*)d_in[1];
    const float* b_in  = (const float*)d_in[2];
    const float* Wq    = (const float*)d_in[3];
    const float* bq    = (const float*)d_in[4];
    const float* W_out = (const float*)d_in[5];
    const float* b_out = (const float*)d_in[6];
    float* out = (float*)d_out;
    qlstm_kernel<<<BB / 2, 256>>>(x, W_in, b_in, Wq, bq, W_out, b_out, out);
}